// round 10
// baseline (speedup 1.0000x reference)
#include <cuda_runtime.h>
#include <math.h>

#define NRAYS   10000
#define NSTEPS  768
#define Zn      32
#define Yn      512
#define Xn      512
#define WPB     8                         // warps per block
#define NBLK    1184                      // 148 SMs * 8 blocks -> one wave
#define GW      (NBLK * WPB)              // 9472 warps; warp-strided over rays

// Per-block partial sums [l1, l2, absrel]. Every block writes its slot each
// launch before any reader -> no init needed.
__device__ float    g_partials[NBLK * 3];
__device__ unsigned g_count = 0;          // reset by the last block each launch

__global__ void __launch_bounds__(WPB * 32)
ray_march_kernel(const float* __restrict__ grid,     // [5,32,512,512] (T,Z,Y,X)
                 const float* __restrict__ origin,   // [5,3]
                 const float* __restrict__ pts,      // [NRAYS,3]
                 const int*   __restrict__ tindex,   // [NRAYS]
                 float*       __restrict__ out)      // [3]
{
    const int warp = threadIdx.x >> 5;
    const int lane = threadIdx.x & 31;
    const int gwid = blockIdx.x * WPB + warp;

    float accL1 = 0.f, accL2 = 0.f, accAR = 0.f;

    for (int ray = gwid; ray < NRAYS; ray += GW) {
        // --- per-ray setup (all lanes redundantly) ---
        const int ti = tindex[ray];
        const float ox = (origin[ti * 3 + 0] + 51.2f) * 5.0f;
        const float oy = (origin[ti * 3 + 1] + 51.2f) * 5.0f;
        const float oz = (origin[ti * 3 + 2] + 3.2f)  * 5.0f;
        const float px = (pts[ray * 3 + 0] + 51.2f) * 5.0f;
        const float py = (pts[ray * 3 + 1] + 51.2f) * 5.0f;
        const float pz = (pts[ray * 3 + 2] + 3.2f)  * 5.0f;

        const float dx = px - ox, dy = py - oy, dz = pz - oz;
        const float gt = sqrtf(dx * dx + dy * dy + dz * dz);
        const float inv = 1.0f / fmaxf(gt, 1e-6f);
        const float ux = dx * inv, uy = dy * inv, uz = dz * inv;

        const float* __restrict__ slice = grid + (size_t)ti * (Zn * Yn * Xn);

        // tau for step at param t (relu'd, 0 if OOB); inb out-param.
        auto sample = [&](float t, bool& inb) -> float {
            const int ix = __float2int_rd(ox + ux * t);
            const int iy = __float2int_rd(oy + uy * t);
            const int iz = __float2int_rd(oz + uz * t);
            inb = ((unsigned)ix < (unsigned)Xn) &
                  ((unsigned)iy < (unsigned)Yn) &
                  ((unsigned)iz < (unsigned)Zn);
            float v = 0.0f;
            if (inb)
                v = fmaxf(__ldg(&slice[((iz * Yn) + iy) * Xn + ix]), 0.0f);
            return v;
        };

        float T     = 1.0f;   // transmittance entering current chunk
        float predL = 0.0f;   // per-lane partial of sum(w * t)

        // 128 steps per iteration: lane l owns steps base+4l .. base+4l+3.
        // After 128 in-bounds steps cum-tau ~51 >> 28, so nearly all rays
        // run exactly one iteration (break by saturation or box exit).
        for (int base = 0; base < NSTEPS; base += 128) {
            const float t0 = (float)(base + 4 * lane) + 0.5f;
            const float t1 = t0 + 1.0f, t2 = t0 + 2.0f, t3 = t0 + 3.0f;
            bool i0, i1, i2, i3;
            const float a0 = sample(t0, i0);   // 4 independent LDGs (MLP=4)
            const float a1 = sample(t1, i1);
            const float a2 = sample(t2, i2);
            const float a3 = sample(t3, i3);

            // inclusive warp scan of per-lane 4-step sums
            const float p = (a0 + a1) + (a2 + a3);
            float cs = p;
            #pragma unroll
            for (int off = 1; off < 32; off <<= 1) {
                float v = __shfl_up_sync(0xffffffffu, cs, off);
                if (lane >= off) cs += v;
            }
            const float excl = cs - p;       // chunk tau before this lane

            const float c1 = excl + a0;
            const float c2 = c1 + a1;
            const float c3 = c2 + a2;
            const float E0 = __expf(-excl);
            const float E1 = __expf(-c1);
            const float E2 = __expf(-c2);
            const float E3 = __expf(-c3);
            const float E4 = __expf(-(c3 + a3));
            // OOB steps have tau=0 -> adjacent E's equal -> 0 contribution.
            predL += T * ((E0 - E1) * t0 + (E1 - E2) * t1 +
                          (E2 - E3) * t2 + (E3 - E4) * t3);

            T *= __shfl_sync(0xffffffffu, E4, 31);   // fold chunk total

            const unsigned bal = __ballot_sync(0xffffffffu, i3);
            // Exit: last step OOB (convex box => exact) or T < 1e-12
            // (dropped contribution < 1e-12 * sum(t) << 1e-3 budget).
            if (!((bal >> 31) & 1u) || T < 1e-12f) break;
        }

        // butterfly reduction of per-lane pred partials
        #pragma unroll
        for (int off = 16; off; off >>= 1)
            predL += __shfl_xor_sync(0xffffffffu, predL, off);

        // per-ray loss terms (gt >= 0 always -> valid, count = NRAYS)
        const float predm = predL * 0.2f;
        const float gtm   = gt * 0.2f;
        const float diff  = gtm - predm;
        accL1 += fabsf(diff);
        accL2 += diff * diff * 0.5f;
        accAR += fabsf(diff) / fmaxf(gtm, 1e-6f);
    }

    // --- per-block reduction across WPB warps (lane-0 scalars) ---
    __shared__ float s1[WPB], s2[WPB], s3[WPB];
    if (lane == 0) { s1[warp] = accL1; s2[warp] = accL2; s3[warp] = accAR; }
    __syncthreads();
    if (threadIdx.x < 32) {
        float a = (lane < WPB) ? s1[lane] : 0.f;
        float b = (lane < WPB) ? s2[lane] : 0.f;
        float d = (lane < WPB) ? s3[lane] : 0.f;
        #pragma unroll
        for (int off = WPB >> 1; off; off >>= 1) {
            a += __shfl_xor_sync(0xffffffffu, a, off);
            b += __shfl_xor_sync(0xffffffffu, b, off);
            d += __shfl_xor_sync(0xffffffffu, d, off);
        }
        if (lane == 0) {
            g_partials[blockIdx.x * 3 + 0] = a;
            g_partials[blockIdx.x * 3 + 1] = b;
            g_partials[blockIdx.x * 3 + 2] = d;
        }
    }

    // --- last-block final reduction (release atomic, no CCTL.IVALL) ---
    __shared__ unsigned s_isLast;
    __syncthreads();
    if (threadIdx.x == 0) {
        unsigned old;
        asm volatile("atom.release.gpu.global.add.u32 %0, [%1], %2;"
                     : "=r"(old) : "l"(&g_count), "r"(1u) : "memory");
        s_isLast = (old == (unsigned)(NBLK - 1));
    }
    __syncthreads();

    if (s_isLast) {
        // Fixed-order strided sums: deterministic regardless of which block
        // executes this. __ldcg reads at L2 (the coherence point).
        float a = 0.f, b = 0.f, d = 0.f;
        for (int i = threadIdx.x; i < NBLK; i += WPB * 32) {
            a += __ldcg(&g_partials[i * 3 + 0]);
            b += __ldcg(&g_partials[i * 3 + 1]);
            d += __ldcg(&g_partials[i * 3 + 2]);
        }
        #pragma unroll
        for (int off = 16; off; off >>= 1) {
            a += __shfl_xor_sync(0xffffffffu, a, off);
            b += __shfl_xor_sync(0xffffffffu, b, off);
            d += __shfl_xor_sync(0xffffffffu, d, off);
        }
        if (lane == 0) { s1[warp] = a; s2[warp] = b; s3[warp] = d; }
        __syncthreads();
        if (threadIdx.x == 0) {
            float ta = 0.f, tb = 0.f, td = 0.f;
            #pragma unroll
            for (int i = 0; i < WPB; i++) { ta += s1[i]; tb += s2[i]; td += s3[i]; }
            const float cnt = (float)NRAYS;
            out[0] = ta / cnt;
            out[1] = tb / cnt;
            out[2] = td / cnt;
            g_count = 0;                 // reset for next graph replay
        }
    }
}

extern "C" void kernel_launch(void* const* d_in, const int* in_sizes, int n_in,
                              void* d_out, int out_size)
{
    const float* grid   = (const float*)d_in[0];   // (1,5,32,512,512) f32
    const float* origin = (const float*)d_in[1];   // (1,5,3) f32
    const float* pts    = (const float*)d_in[2];   // (1,10000,3) f32
    const int*   tidx   = (const int*)d_in[3];     // (1,10000) i32
    float* out = (float*)d_out;                    // 3 floats

    ray_march_kernel<<<NBLK, WPB * 32>>>(grid, origin, pts, tidx, out);
}